// round 4
// baseline (speedup 1.0000x reference)
#include <cuda_runtime.h>
#include <cuda_bf16.h>
#include <math.h>

#define NN 50000
#define EE 800000
#define ETOT (EE + NN)   // edges + self loops = 850000
#define D 64
#define HH 4
#define CC 16
#define LL 3
#define FF 8
#define TEE 16

// ---------------- scratch (device globals; no allocs allowed) ----------------
__device__ float g_h[NN * D];
__device__ float g_h0[NN * D];
__device__ float g_xl[NN * D];
__device__ float g_xr[NN * D];
__device__ float g_xres[NN * D];
__device__ int   g_deg[NN];
__device__ int   g_rowptr[NN + 1];
__device__ int   g_cursor[NN];
__device__ int   g_col[ETOT];

// ---------------- input projection: h0 = (relu(x@Wt+bt) ++ Et[type]) @ Wp + bp
__global__ void k_input_proj(const float* __restrict__ x,
                             const int* __restrict__ ntype,
                             const float* __restrict__ Wt, const float* __restrict__ bt,
                             const float* __restrict__ Et,
                             const float* __restrict__ Wp, const float* __restrict__ bp)
{
    __shared__ float sWt[FF * D];
    __shared__ float sWp[(D + TEE) * D];
    __shared__ float sbt[D], sbp[D];
    __shared__ float sEt[3 * TEE];
    __shared__ float stmp[4][D + TEE];

    int tid = threadIdx.x;
    for (int i = tid; i < FF * D; i += 256) sWt[i] = Wt[i];
    for (int i = tid; i < (D + TEE) * D; i += 256) sWp[i] = Wp[i];
    if (tid < D) { sbt[tid] = bt[tid]; sbp[tid] = bp[tid]; }
    if (tid < 3 * TEE) sEt[tid] = Et[tid];
    __syncthreads();

    int slot = tid >> 6;
    int j = tid & 63;
    for (int n0 = blockIdx.x * 4; n0 < NN; n0 += gridDim.x * 4) {
        int n = n0 + slot;
        if (n < NN) {
            float acc = sbt[j];
            #pragma unroll
            for (int f = 0; f < FF; f++) acc += x[n * FF + f] * sWt[f * D + j];
            stmp[slot][j] = fmaxf(acc, 0.0f);
            if (j < TEE) stmp[slot][D + j] = sEt[ntype[n] * TEE + j];
        }
        __syncthreads();
        if (n < NN) {
            float acc = sbp[j];
            #pragma unroll 8
            for (int k = 0; k < D + TEE; k++) acc += stmp[slot][k] * sWp[k * D + j];
            g_h[n * D + j] = acc;
            g_h0[n * D + j] = acc;
        }
        __syncthreads();
    }
}

// ---------------- CSR build by destination ----------------
__global__ void k_zero_deg()
{
    for (int i = blockIdx.x * blockDim.x + threadIdx.x; i < NN; i += gridDim.x * blockDim.x)
        g_deg[i] = 0;
}

__global__ void k_hist(const int* __restrict__ dst)
{
    for (int e = blockIdx.x * blockDim.x + threadIdx.x; e < ETOT; e += gridDim.x * blockDim.x) {
        int d = (e < EE) ? dst[e] : (e - EE);
        atomicAdd(&g_deg[d], 1);
    }
}

__global__ void k_scan()   // single block, 1024 threads
{
    __shared__ int part[1024];
    const int CH = (NN + 1023) / 1024;
    int tid = threadIdx.x;
    int base = tid * CH;
    int sum = 0;
    for (int i = 0; i < CH; i++) {
        int idx = base + i;
        if (idx < NN) sum += g_deg[idx];
    }
    part[tid] = sum;
    __syncthreads();
    for (int off = 1; off < 1024; off <<= 1) {
        int v = (tid >= off) ? part[tid - off] : 0;
        __syncthreads();
        part[tid] += v;
        __syncthreads();
    }
    int run = part[tid] - sum;   // exclusive prefix of this chunk
    for (int i = 0; i < CH; i++) {
        int idx = base + i;
        if (idx < NN) {
            g_rowptr[idx] = run;
            g_cursor[idx] = run;
            run += g_deg[idx];
        }
    }
    if (tid == 0) g_rowptr[NN] = ETOT;
}

__global__ void k_scatter(const int* __restrict__ src, const int* __restrict__ dst)
{
    for (int e = blockIdx.x * blockDim.x + threadIdx.x; e < ETOT; e += gridDim.x * blockDim.x) {
        int s, d;
        if (e < EE) { s = src[e]; d = dst[e]; }
        else        { s = d = e - EE; }
        int slot = atomicAdd(&g_cursor[d], 1);
        g_col[slot] = s;
    }
}

// ---------------- per-layer triple GEMM: xl = h@Wl+bl, xr = h@Wr+br, xres = h@Wres+bconv
__global__ void k_gemm3(const float* __restrict__ Wl, const float* __restrict__ bl,
                        const float* __restrict__ Wr, const float* __restrict__ br,
                        const float* __restrict__ Wres, const float* __restrict__ bc,
                        int l)
{
    extern __shared__ float sm[];
    float* sA = sm;              // 4096
    float* sB = sm + 4096;       // 4096
    float* sC = sm + 8192;       // 4096
    float* sh = sm + 12288;      // 4*64

    int tid = threadIdx.x;
    const float* Al = Wl + l * 4096;
    const float* Bl = Wr + l * 4096;
    const float* Cl = Wres + l * 4096;
    for (int i = tid; i < 4096; i += 256) {
        sA[i] = Al[i]; sB[i] = Bl[i]; sC[i] = Cl[i];
    }
    __syncthreads();

    int slot = tid >> 6;
    int j = tid & 63;
    float bL = bl[l * D + j];
    float bR = br[l * D + j];
    float bS = bc[l * D + j];

    for (int n0 = blockIdx.x * 4; n0 < NN; n0 += gridDim.x * 4) {
        int n = n0 + slot;
        if (n < NN) sh[slot * D + j] = g_h[n * D + j];
        __syncthreads();
        if (n < NN) {
            float aL = bL, aR = bR, aS = bS;
            #pragma unroll 16
            for (int k = 0; k < D; k++) {
                float hk = sh[slot * D + k];
                aL += hk * sA[k * D + j];
                aR += hk * sB[k * D + j];
                aS += hk * sC[k * D + j];
            }
            g_xl[n * D + j] = aL;
            g_xr[n * D + j] = aR;
            g_xres[n * D + j] = aS;
        }
        __syncthreads();
    }
}

// ---------------- GAT layer: warp per destination node, online softmax, fused LN
__global__ void k_gat(const float* __restrict__ att,
                      const float* __restrict__ gamma, const float* __restrict__ beta,
                      const float* __restrict__ alpha_p, int l)
{
    int warp = threadIdx.x >> 5;
    int lane = threadIdx.x & 31;
    int n = blockIdx.x * (blockDim.x >> 5) + warp;
    if (n >= NN) return;

    int head = lane >> 3;            // lanes 8h..8h+7 cover head h
    int c0 = (2 * lane) & 15;
    float a0 = att[l * (HH * CC) + head * CC + c0];
    float a1 = att[l * (HH * CC) + head * CC + c0 + 1];

    float2 xr2 = *reinterpret_cast<const float2*>(&g_xr[n * D + 2 * lane]);
    int beg = g_rowptr[n];
    int end = g_rowptr[n + 1];

    // sweep 1: online softmax (max + rescaled sum), per head (replicated over 8 lanes)
    float m = -1e30f, s = 0.0f;
    for (int e = beg; e < end; e++) {
        int src = g_col[e];
        float2 xl2 = *reinterpret_cast<const float2*>(&g_xl[src * D + 2 * lane]);
        float v0 = xl2.x + xr2.x; v0 = v0 > 0.0f ? v0 : 0.2f * v0;
        float v1 = xl2.y + xr2.y; v1 = v1 > 0.0f ? v1 : 0.2f * v1;
        float p = a0 * v0 + a1 * v1;
        p += __shfl_xor_sync(0xffffffffu, p, 1);
        p += __shfl_xor_sync(0xffffffffu, p, 2);
        p += __shfl_xor_sync(0xffffffffu, p, 4);
        float nm = fmaxf(m, p);
        s = s * __expf(m - nm) + __expf(p - nm);
        m = nm;
    }
    float inv_s = 1.0f / (s + 1e-16f);

    // sweep 2: weighted aggregation
    float acc0 = 0.0f, acc1 = 0.0f;
    for (int e = beg; e < end; e++) {
        int src = g_col[e];
        float2 xl2 = *reinterpret_cast<const float2*>(&g_xl[src * D + 2 * lane]);
        float v0 = xl2.x + xr2.x; v0 = v0 > 0.0f ? v0 : 0.2f * v0;
        float v1 = xl2.y + xr2.y; v1 = v1 > 0.0f ? v1 : 0.2f * v1;
        float p = a0 * v0 + a1 * v1;
        p += __shfl_xor_sync(0xffffffffu, p, 1);
        p += __shfl_xor_sync(0xffffffffu, p, 2);
        p += __shfl_xor_sync(0xffffffffu, p, 4);
        float w = __expf(p - m) * inv_s;
        acc0 += xl2.x * w;
        acc1 += xl2.y * w;
    }

    // epilogue: residual GEMM term + skip + LayerNorm, all in-warp
    float2 xres2 = *reinterpret_cast<const float2*>(&g_xres[n * D + 2 * lane]);
    float2 h02 = *reinterpret_cast<const float2*>(&g_h0[n * D + 2 * lane]);
    float al = *alpha_p;
    float v0 = al * (acc0 + xres2.x) + (1.0f - al) * h02.x;
    float v1 = al * (acc1 + xres2.y) + (1.0f - al) * h02.y;

    float sum = v0 + v1;
    float sq = v0 * v0 + v1 * v1;
    #pragma unroll
    for (int off = 16; off >= 1; off >>= 1) {
        sum += __shfl_xor_sync(0xffffffffu, sum, off);
        sq  += __shfl_xor_sync(0xffffffffu, sq, off);
    }
    float mu = sum * (1.0f / D);
    float var = sq * (1.0f / D) - mu * mu;
    float inv = rsqrtf(var + 1e-5f);

    float g0 = gamma[l * D + 2 * lane], g1 = gamma[l * D + 2 * lane + 1];
    float b0 = beta[l * D + 2 * lane],  b1 = beta[l * D + 2 * lane + 1];
    float2 outv;
    outv.x = g0 * (v0 - mu) * inv + b0;
    outv.y = g1 * (v1 - mu) * inv + b1;
    *reinterpret_cast<float2*>(&g_h[n * D + 2 * lane]) = outv;
}

// ---------------- output head: sigmoid(relu(h@W1+b1)@W2+b2) ----------------
__global__ void k_head(const float* __restrict__ W1, const float* __restrict__ b1,
                       const float* __restrict__ W2, const float* __restrict__ b2,
                       float* __restrict__ out)
{
    __shared__ float sW1[D * 32];
    __shared__ float sW2[32];
    __shared__ float sb1[32];
    int tid = threadIdx.x;
    for (int i = tid; i < D * 32; i += 256) sW1[i] = W1[i];
    if (tid < 32) { sW2[tid] = W2[tid]; sb1[tid] = b1[tid]; }
    __syncthreads();

    int warp = tid >> 5;
    int lane = tid & 31;
    float b2v = b2[0];
    for (int n = blockIdx.x * 8 + warp; n < NN; n += gridDim.x * 8) {
        float acc = sb1[lane];
        const float* hr = &g_h[n * D];
        #pragma unroll 16
        for (int k = 0; k < D; k++) acc += hr[k] * sW1[k * 32 + lane];
        float z = fmaxf(acc, 0.0f);
        float p = z * sW2[lane];
        #pragma unroll
        for (int off = 16; off >= 1; off >>= 1)
            p += __shfl_xor_sync(0xffffffffu, p, off);
        if (lane == 0) out[n] = 1.0f / (1.0f + __expf(-(p + b2v)));
    }
}

// ---------------- launch ----------------
extern "C" void kernel_launch(void* const* d_in, const int* in_sizes, int n_in,
                              void* d_out, int out_size)
{
    const float* x        = (const float*)d_in[0];
    const int*   ntype    = (const int*)d_in[1];
    const int*   esrc     = (const int*)d_in[2];
    const int*   edst     = (const int*)d_in[3];
    const float* Wt       = (const float*)d_in[4];
    const float* bt       = (const float*)d_in[5];
    const float* Et       = (const float*)d_in[6];
    const float* Wp       = (const float*)d_in[7];
    const float* bp       = (const float*)d_in[8];
    const float* Wl       = (const float*)d_in[9];
    const float* bl       = (const float*)d_in[10];
    const float* Wr       = (const float*)d_in[11];
    const float* br       = (const float*)d_in[12];
    const float* att      = (const float*)d_in[13];
    const float* Wres     = (const float*)d_in[14];
    const float* bconv    = (const float*)d_in[15];
    const float* gamma    = (const float*)d_in[16];
    const float* beta     = (const float*)d_in[17];
    const float* alpha    = (const float*)d_in[18];
    const float* W1       = (const float*)d_in[19];
    const float* b1       = (const float*)d_in[20];
    const float* W2       = (const float*)d_in[21];
    const float* b2       = (const float*)d_in[22];
    float* out = (float*)d_out;

    static bool attr_set = false;  // idempotent attribute opt-in (not a guard on work)
    const int gemm3_smem = (3 * 4096 + 4 * D) * sizeof(float);
    if (!attr_set) {
        cudaFuncSetAttribute(k_gemm3, cudaFuncAttributeMaxDynamicSharedMemorySize, gemm3_smem);
        attr_set = true;
    }

    // input projection
    k_input_proj<<<400, 256>>>(x, ntype, Wt, bt, Et, Wp, bp);

    // CSR build (every call; deterministic up to fp tolerance)
    k_zero_deg<<<64, 256>>>();
    k_hist<<<1024, 256>>>(edst);
    k_scan<<<1, 1024>>>();
    k_scatter<<<1024, 256>>>(esrc, edst);

    // GAT layers
    for (int l = 0; l < LL; l++) {
        k_gemm3<<<400, 256, gemm3_smem>>>(Wl, bl, Wr, br, Wres, bconv, l);
        k_gat<<<(NN + 7) / 8, 256>>>(att, gamma, beta, alpha, l);
    }

    // output head
    k_head<<<(NN + 7) / 8, 256>>>(W1, b1, W2, b2, out);
}

// round 7
// speedup vs baseline: 1.8394x; 1.8394x over previous
#include <cuda_runtime.h>
#include <cuda_bf16.h>
#include <math.h>

#define NN 50000
#define EE 800000
#define ETOT (EE + NN)   // edges + self loops = 850000
#define D 64
#define HH 4
#define CC 16
#define LL 3
#define FF 8
#define TEE 16

// ---------------- scratch (device globals; no allocs allowed) ----------------
__device__ float g_h[NN * D];
__device__ float g_h0[NN * D];
__device__ float g_xl[NN * D];
__device__ float g_xr[NN * D];
__device__ float g_xres[NN * D];
__device__ int   g_deg[NN];
__device__ int   g_rowptr[NN + 1];
__device__ int   g_cursor[NN];
__device__ int   g_col[ETOT];
__device__ int   g_bsum[256];

// ---------------- input projection: h0 = (relu(x@Wt+bt) ++ Et[type]) @ Wp + bp
__global__ void k_input_proj(const float* __restrict__ x,
                             const int* __restrict__ ntype,
                             const float* __restrict__ Wt, const float* __restrict__ bt,
                             const float* __restrict__ Et,
                             const float* __restrict__ Wp, const float* __restrict__ bp)
{
    __shared__ float sWt[FF * D];
    __shared__ float sWp[(D + TEE) * D];
    __shared__ float sbt[D], sbp[D];
    __shared__ float sEt[3 * TEE];
    __shared__ float stmp[4][D + TEE];

    int tid = threadIdx.x;
    for (int i = tid; i < FF * D; i += 256) sWt[i] = Wt[i];
    for (int i = tid; i < (D + TEE) * D; i += 256) sWp[i] = Wp[i];
    if (tid < D) { sbt[tid] = bt[tid]; sbp[tid] = bp[tid]; }
    if (tid < 3 * TEE) sEt[tid] = Et[tid];
    __syncthreads();

    int slot = tid >> 6;
    int j = tid & 63;
    for (int n0 = blockIdx.x * 4; n0 < NN; n0 += gridDim.x * 4) {
        int n = n0 + slot;
        if (n < NN) {
            float acc = sbt[j];
            #pragma unroll
            for (int f = 0; f < FF; f++) acc += x[n * FF + f] * sWt[f * D + j];
            stmp[slot][j] = fmaxf(acc, 0.0f);
            if (j < TEE) stmp[slot][D + j] = sEt[ntype[n] * TEE + j];
        }
        __syncthreads();
        if (n < NN) {
            float acc = sbp[j];
            #pragma unroll 8
            for (int k = 0; k < D + TEE; k++) acc += stmp[slot][k] * sWp[k * D + j];
            g_h[n * D + j] = acc;
            g_h0[n * D + j] = acc;
        }
        __syncthreads();
    }
}

// ---------------- CSR build by destination ----------------
__global__ void k_zero_deg()
{
    for (int i = blockIdx.x * blockDim.x + threadIdx.x; i < NN; i += gridDim.x * blockDim.x)
        g_deg[i] = 0;
}

__global__ void k_hist(const int* __restrict__ dst)
{
    for (int e = blockIdx.x * blockDim.x + threadIdx.x; e < ETOT; e += gridDim.x * blockDim.x) {
        int d = (e < EE) ? dst[e] : (e - EE);
        atomicAdd(&g_deg[d], 1);
    }
}

// --- parallel 3-phase scan: 256 blocks x 256 threads covers 65536 >= NN ---
__global__ void k_scan1()   // per-block exclusive scan; write local prefix + block sum
{
    __shared__ int sh[256];
    int tid = threadIdx.x;
    int i = blockIdx.x * 256 + tid;
    int v = (i < NN) ? g_deg[i] : 0;
    sh[tid] = v;
    __syncthreads();
    int acc = v;
    #pragma unroll
    for (int off = 1; off < 256; off <<= 1) {
        int t = (tid >= off) ? sh[tid - off] : 0;
        __syncthreads();
        acc += t;
        sh[tid] = acc;
        __syncthreads();
    }
    if (i < NN) g_rowptr[i] = acc - v;   // exclusive (local)
    if (tid == 255) g_bsum[blockIdx.x] = acc;
}

__global__ void k_scan2()   // 1 block, 256 threads: exclusive scan of block sums
{
    __shared__ int sh[256];
    int tid = threadIdx.x;
    int v = g_bsum[tid];
    sh[tid] = v;
    __syncthreads();
    int acc = v;
    #pragma unroll
    for (int off = 1; off < 256; off <<= 1) {
        int t = (tid >= off) ? sh[tid - off] : 0;
        __syncthreads();
        acc += t;
        sh[tid] = acc;
        __syncthreads();
    }
    g_bsum[tid] = acc - v;  // exclusive
}

__global__ void k_scan3()   // add block offset, init cursor, cap rowptr
{
    int i = blockIdx.x * 256 + threadIdx.x;
    if (i < NN) {
        int r = g_rowptr[i] + g_bsum[blockIdx.x];
        g_rowptr[i] = r;
        g_cursor[i] = r;
    }
    if (i == 0) g_rowptr[NN] = ETOT;
}

__global__ void k_scatter(const int* __restrict__ src, const int* __restrict__ dst)
{
    for (int e = blockIdx.x * blockDim.x + threadIdx.x; e < ETOT; e += gridDim.x * blockDim.x) {
        int s, d;
        if (e < EE) { s = src[e]; d = dst[e]; }
        else        { s = d = e - EE; }
        int slot = atomicAdd(&g_cursor[d], 1);
        g_col[slot] = s;
    }
}

// ---------------- per-layer triple GEMM, register-blocked 8 nodes / slot -----
// xl = h@Wl+bl, xr = h@Wr+br, xres = h@Wres+bconv
#define GT_STRIDE 36   // padded row stride for transposed h tile (floats)
__global__ void k_gemm3(const float* __restrict__ Wl, const float* __restrict__ bl,
                        const float* __restrict__ Wr, const float* __restrict__ br,
                        const float* __restrict__ Wres, const float* __restrict__ bc,
                        int l)
{
    extern __shared__ float sm[];
    float* sA = sm;               // 4096
    float* sB = sm + 4096;        // 4096
    float* sC = sm + 8192;        // 4096
    float* shT = sm + 12288;      // [64][GT_STRIDE] transposed: shT[k][node]

    int tid = threadIdx.x;
    const float* Al = Wl + l * 4096;
    const float* Bl = Wr + l * 4096;
    const float* Cl = Wres + l * 4096;
    for (int i = tid; i < 4096; i += 256) {
        sA[i] = Al[i]; sB[i] = Bl[i]; sC[i] = Cl[i];
    }

    int slot = tid >> 6;          // 0..3, each handles 8 nodes
    int j = tid & 63;             // output column
    float bL = bl[l * D + j];
    float bR = br[l * D + j];
    float bS = bc[l * D + j];
    __syncthreads();

    for (int n0 = blockIdx.x * 32; n0 < NN; n0 += gridDim.x * 32) {
        // load 32 nodes' h, transposed: shT[j][node] (j is the k-dimension here)
        #pragma unroll
        for (int i = 0; i < 8; i++) {
            int node = slot * 8 + i;
            int n = n0 + node;
            shT[j * GT_STRIDE + node] = (n < NN) ? g_h[n * D + j] : 0.0f;
        }
        __syncthreads();

        float aL[8], aR[8], aS[8];
        #pragma unroll
        for (int i = 0; i < 8; i++) { aL[i] = bL; aR[i] = bR; aS[i] = bS; }

        #pragma unroll 4
        for (int k = 0; k < D; k++) {
            float4 hA = *reinterpret_cast<const float4*>(&shT[k * GT_STRIDE + slot * 8]);
            float4 hB = *reinterpret_cast<const float4*>(&shT[k * GT_STRIDE + slot * 8 + 4]);
            float wl = sA[k * D + j];
            float wr = sB[k * D + j];
            float ws = sC[k * D + j];
            aL[0] += hA.x * wl; aL[1] += hA.y * wl; aL[2] += hA.z * wl; aL[3] += hA.w * wl;
            aL[4] += hB.x * wl; aL[5] += hB.y * wl; aL[6] += hB.z * wl; aL[7] += hB.w * wl;
            aR[0] += hA.x * wr; aR[1] += hA.y * wr; aR[2] += hA.z * wr; aR[3] += hA.w * wr;
            aR[4] += hB.x * wr; aR[5] += hB.y * wr; aR[6] += hB.z * wr; aR[7] += hB.w * wr;
            aS[0] += hA.x * ws; aS[1] += hA.y * ws; aS[2] += hA.z * ws; aS[3] += hA.w * ws;
            aS[4] += hB.x * ws; aS[5] += hB.y * ws; aS[6] += hB.z * ws; aS[7] += hB.w * ws;
        }

        #pragma unroll
        for (int i = 0; i < 8; i++) {
            int n = n0 + slot * 8 + i;
            if (n < NN) {
                g_xl[n * D + j]   = aL[i];
                g_xr[n * D + j]   = aR[i];
                g_xres[n * D + j] = aS[i];
            }
        }
        __syncthreads();
    }
}

// ---------------- GAT layer: warp per node, single-sweep flash softmax, fused LN
__global__ void k_gat(const float* __restrict__ att,
                      const float* __restrict__ gamma, const float* __restrict__ beta,
                      const float* __restrict__ alpha_p, int l)
{
    int warp = threadIdx.x >> 5;
    int lane = threadIdx.x & 31;
    int n = blockIdx.x * (blockDim.x >> 5) + warp;
    if (n >= NN) return;

    int head = lane >> 3;            // lanes 8h..8h+7 cover head h
    int c0 = (2 * lane) & 15;
    float a0 = att[l * (HH * CC) + head * CC + c0];
    float a1 = att[l * (HH * CC) + head * CC + c0 + 1];

    float2 xr2 = *reinterpret_cast<const float2*>(&g_xr[n * D + 2 * lane]);
    int beg = g_rowptr[n];
    int end = g_rowptr[n + 1];

    // two independent flash-softmax chains (even/odd edges) for ILP
    float mA = -1e30f, sA = 0.0f, accA0 = 0.0f, accA1 = 0.0f;
    float mB = -1e30f, sB = 0.0f, accB0 = 0.0f, accB1 = 0.0f;

    for (int e = beg; e < end; e += 2) {
        int has1 = (e + 1 < end);
        int s0 = g_col[e];
        int s1 = has1 ? g_col[e + 1] : s0;
        float2 x0 = *reinterpret_cast<const float2*>(&g_xl[s0 * D + 2 * lane]);
        float2 x1 = *reinterpret_cast<const float2*>(&g_xl[s1 * D + 2 * lane]);

        // chain A
        {
            float v0 = x0.x + xr2.x; v0 = v0 > 0.0f ? v0 : 0.2f * v0;
            float v1 = x0.y + xr2.y; v1 = v1 > 0.0f ? v1 : 0.2f * v1;
            float p = a0 * v0 + a1 * v1;
            p += __shfl_xor_sync(0xffffffffu, p, 1);
            p += __shfl_xor_sync(0xffffffffu, p, 2);
            p += __shfl_xor_sync(0xffffffffu, p, 4);
            float nm = fmaxf(mA, p);
            float f = __expf(mA - nm);
            float w = __expf(p - nm);
            sA = sA * f + w;
            accA0 = accA0 * f + x0.x * w;
            accA1 = accA1 * f + x0.y * w;
            mA = nm;
        }
        // chain B (uniform branch across warp)
        if (has1) {
            float v0 = x1.x + xr2.x; v0 = v0 > 0.0f ? v0 : 0.2f * v0;
            float v1 = x1.y + xr2.y; v1 = v1 > 0.0f ? v1 : 0.2f * v1;
            float p = a0 * v0 + a1 * v1;
            p += __shfl_xor_sync(0xffffffffu, p, 1);
            p += __shfl_xor_sync(0xffffffffu, p, 2);
            p += __shfl_xor_sync(0xffffffffu, p, 4);
            float nm = fmaxf(mB, p);
            float f = __expf(mB - nm);
            float w = __expf(p - nm);
            sB = sB * f + w;
            accB0 = accB0 * f + x1.x * w;
            accB1 = accB1 * f + x1.y * w;
            mB = nm;
        }
    }

    // merge chains
    float m = fmaxf(mA, mB);
    float fA = __expf(mA - m);
    float fB = __expf(mB - m);
    float s = sA * fA + sB * fB;
    float acc0 = accA0 * fA + accB0 * fB;
    float acc1 = accA1 * fA + accB1 * fB;
    float inv_s = 1.0f / (s + 1e-16f);
    acc0 *= inv_s;
    acc1 *= inv_s;

    // epilogue: residual GEMM term + skip + LayerNorm, all in-warp
    float2 xres2 = *reinterpret_cast<const float2*>(&g_xres[n * D + 2 * lane]);
    float2 h02 = *reinterpret_cast<const float2*>(&g_h0[n * D + 2 * lane]);
    float al = *alpha_p;
    float v0 = al * (acc0 + xres2.x) + (1.0f - al) * h02.x;
    float v1 = al * (acc1 + xres2.y) + (1.0f - al) * h02.y;

    float sum = v0 + v1;
    float sq = v0 * v0 + v1 * v1;
    #pragma unroll
    for (int off = 16; off >= 1; off >>= 1) {
        sum += __shfl_xor_sync(0xffffffffu, sum, off);
        sq  += __shfl_xor_sync(0xffffffffu, sq, off);
    }
    float mu = sum * (1.0f / D);
    float var = sq * (1.0f / D) - mu * mu;
    float inv = rsqrtf(var + 1e-5f);

    float g0 = gamma[l * D + 2 * lane], g1 = gamma[l * D + 2 * lane + 1];
    float b0 = beta[l * D + 2 * lane],  b1 = beta[l * D + 2 * lane + 1];
    float2 outv;
    outv.x = g0 * (v0 - mu) * inv + b0;
    outv.y = g1 * (v1 - mu) * inv + b1;
    *reinterpret_cast<float2*>(&g_h[n * D + 2 * lane]) = outv;
}

// ---------------- output head: sigmoid(relu(h@W1+b1)@W2+b2) ----------------
__global__ void k_head(const float* __restrict__ W1, const float* __restrict__ b1,
                       const float* __restrict__ W2, const float* __restrict__ b2,
                       float* __restrict__ out)
{
    __shared__ float sW1[D * 32];
    __shared__ float sW2[32];
    __shared__ float sb1[32];
    int tid = threadIdx.x;
    for (int i = tid; i < D * 32; i += 256) sW1[i] = W1[i];
    if (tid < 32) { sW2[tid] = W2[tid]; sb1[tid] = b1[tid]; }
    __syncthreads();

    int warp = tid >> 5;
    int lane = tid & 31;
    float b2v = b2[0];
    for (int n = blockIdx.x * 8 + warp; n < NN; n += gridDim.x * 8) {
        float acc = sb1[lane];
        const float* hr = &g_h[n * D];
        #pragma unroll 16
        for (int k = 0; k < D; k++) acc += hr[k] * sW1[k * 32 + lane];
        float z = fmaxf(acc, 0.0f);
        float p = z * sW2[lane];
        #pragma unroll
        for (int off = 16; off >= 1; off >>= 1)
            p += __shfl_xor_sync(0xffffffffu, p, off);
        if (lane == 0) out[n] = 1.0f / (1.0f + __expf(-(p + b2v)));
    }
}

// ---------------- launch ----------------
extern "C" void kernel_launch(void* const* d_in, const int* in_sizes, int n_in,
                              void* d_out, int out_size)
{
    const float* x        = (const float*)d_in[0];
    const int*   ntype    = (const int*)d_in[1];
    const int*   esrc     = (const int*)d_in[2];
    const int*   edst     = (const int*)d_in[3];
    const float* Wt       = (const float*)d_in[4];
    const float* bt       = (const float*)d_in[5];
    const float* Et       = (const float*)d_in[6];
    const float* Wp       = (const float*)d_in[7];
    const float* bp       = (const float*)d_in[8];
    const float* Wl       = (const float*)d_in[9];
    const float* bl       = (const float*)d_in[10];
    const float* Wr       = (const float*)d_in[11];
    const float* br       = (const float*)d_in[12];
    const float* att      = (const float*)d_in[13];
    const float* Wres     = (const float*)d_in[14];
    const float* bconv    = (const float*)d_in[15];
    const float* gamma    = (const float*)d_in[16];
    const float* beta     = (const float*)d_in[17];
    const float* alpha    = (const float*)d_in[18];
    const float* W1       = (const float*)d_in[19];
    const float* b1       = (const float*)d_in[20];
    const float* W2       = (const float*)d_in[21];
    const float* b2       = (const float*)d_in[22];
    float* out = (float*)d_out;

    static bool attr_set = false;  // idempotent attribute opt-in (not a guard on work)
    const int gemm3_smem = (3 * 4096 + 64 * GT_STRIDE) * sizeof(float);
    if (!attr_set) {
        cudaFuncSetAttribute(k_gemm3, cudaFuncAttributeMaxDynamicSharedMemorySize, gemm3_smem);
        attr_set = true;
    }

    // input projection
    k_input_proj<<<400, 256>>>(x, ntype, Wt, bt, Et, Wp, bp);

    // CSR build (every call; deterministic up to fp tolerance)
    k_zero_deg<<<64, 256>>>();
    k_hist<<<1024, 256>>>(edst);
    k_scan1<<<256, 256>>>();
    k_scan2<<<1, 256>>>();
    k_scan3<<<256, 256>>>();
    k_scatter<<<1024, 256>>>(esrc, edst);

    // GAT layers
    for (int l = 0; l < LL; l++) {
        k_gemm3<<<444, 256, gemm3_smem>>>(Wl, bl, Wr, br, Wres, bconv, l);
        k_gat<<<(NN + 7) / 8, 256>>>(att, gamma, beta, alpha, l);
    }

    // output head
    k_head<<<(NN + 7) / 8, 256>>>(W1, b1, W2, b2, out);
}